// round 2
// baseline (speedup 1.0000x reference)
#include <cuda_runtime.h>
#include <math.h>

// Problem constants
#define D_    64
#define L_    64
#define M_    192          // 3*L nodes per dialogue
#define DIM_  512
#define G_    256
#define N_    4096         // D*L
#define KTOP  12           // int(64*0.2)
#define INV_TAU (1.0f/0.07f)

// ---------------- scratch (static __device__ arrays: allocation-free) ------
__device__ float g_feat[D_*M_*DIM_];   // [d, jm, f]
__device__ float g_gram[D_*M_*M_];     // per-dialogue gram
__device__ float g_H[D_*M_*M_];        // incidence (0/1)
__device__ float g_dege[D_*M_];
__device__ float g_degv[D_*M_];
__device__ float g_X[D_*M_*G_];
__device__ float g_E[D_*M_*G_];
__device__ float g_Y[D_*M_*G_];
__device__ float g_xn[3*N_*G_];        // normalized tn/an/vn
__device__ float g_rowsum[3*N_];
__device__ float g_colsum[3*N_];
__device__ float g_lossacc;

// ---------------- feat packing ---------------------------------------------
__global__ void pack_kernel(const float* __restrict__ t,
                            const float* __restrict__ a,
                            const float* __restrict__ v) {
    int gid = blockIdx.x * 256 + threadIdx.x;   // float4 index, 12288*128 total
    int row = gid >> 7;
    int c   = gid & 127;
    int d   = row / M_;
    int jm  = row % M_;
    const float* src = (jm < L_) ? t : (jm < 2*L_) ? a : v;
    int srow = d * L_ + (jm & 63);
    float4 val = ((const float4*)src)[(long)srow * 128 + c];
    ((float4*)g_feat)[(long)row * 128 + c] = val;
}

// ---------------- generic tiled GEMM ---------------------------------------
// TA: 0 => A[m*lda+k], 1 => A[k*lda+m].  TB: 0 => B[k*ldb+n], 1 => B[n*ldb+k]
// EPI: 0 plain, 1 +bias, 2 /divrow[b*M+row], 3 +bias,relu,remap->out_cat
template<int TA, int TB, int EPI>
__global__ __launch_bounds__(256)
void gemm_k(const float* __restrict__ Ag, const float* __restrict__ Bg,
            float* __restrict__ Cg,
            int M, int N, int K, int lda, int ldb,
            long sA, long sB, long sC,
            const float* __restrict__ bias,
            const float* __restrict__ divrow,
            float* __restrict__ outp) {
    __shared__ float As[16][64];
    __shared__ float Bs[16][64];
    const int b = blockIdx.z;
    const float* A = Ag + (long)b * sA;
    const float* B = Bg + (long)b * sB;
    const int m0 = blockIdx.y * 64;
    const int n0 = blockIdx.x * 64;
    const int tid = threadIdx.x;
    const int tx = tid & 15, ty = tid >> 4;
    float acc[4][4];
    #pragma unroll
    for (int i = 0; i < 4; i++)
        #pragma unroll
        for (int j = 0; j < 4; j++) acc[i][j] = 0.f;

    for (int k0 = 0; k0 < K; k0 += 16) {
        if (TA == 0) {
            int m = tid >> 2, k = (tid & 3) << 2;
            float4 t4 = *(const float4*)(A + (long)(m0 + m) * lda + k0 + k);
            As[k+0][m] = t4.x; As[k+1][m] = t4.y; As[k+2][m] = t4.z; As[k+3][m] = t4.w;
        } else {
            int k = tid >> 4, m = (tid & 15) << 2;
            *(float4*)&As[k][m] = *(const float4*)(A + (long)(k0 + k) * lda + m0 + m);
        }
        if (TB == 0) {
            int k = tid >> 4, n = (tid & 15) << 2;
            *(float4*)&Bs[k][n] = *(const float4*)(B + (long)(k0 + k) * ldb + n0 + n);
        } else {
            int n = tid >> 2, k = (tid & 3) << 2;
            float4 t4 = *(const float4*)(B + (long)(n0 + n) * ldb + k0 + k);
            Bs[k+0][n] = t4.x; Bs[k+1][n] = t4.y; Bs[k+2][n] = t4.z; Bs[k+3][n] = t4.w;
        }
        __syncthreads();
        #pragma unroll
        for (int k = 0; k < 16; k++) {
            float4 av = *(const float4*)&As[k][ty << 2];
            float4 bv = *(const float4*)&Bs[k][tx << 2];
            float aa[4] = {av.x, av.y, av.z, av.w};
            float bb[4] = {bv.x, bv.y, bv.z, bv.w};
            #pragma unroll
            for (int i = 0; i < 4; i++)
                #pragma unroll
                for (int j = 0; j < 4; j++)
                    acc[i][j] = fmaf(aa[i], bb[j], acc[i][j]);
        }
        __syncthreads();
    }

    #pragma unroll
    for (int i = 0; i < 4; i++) {
        int row = m0 + (ty << 2) + i;
        float dr = 1.f;
        if (EPI == 2) dr = divrow[(long)b * M + row];
        float vals[4];
        #pragma unroll
        for (int j = 0; j < 4; j++) {
            int col = n0 + (tx << 2) + j;
            float x = acc[i][j];
            if (EPI == 1 || EPI == 3) x += bias[col];
            if (EPI == 2) x = x / dr;
            if (EPI == 3) x = fmaxf(x, 0.f);
            vals[j] = x;
        }
        float4 o = make_float4(vals[0], vals[1], vals[2], vals[3]);
        if (EPI == 3) {
            int d = row / M_, jm = row % M_;
            long base = ((long)(d * L_ + (jm & 63)) * (3 * G_)) + (jm >> 6) * G_ + n0 + (tx << 2);
            *(float4*)(outp + base) = o;
        } else {
            float* Cb = Cg + (long)b * sC;
            *(float4*)(Cb + (long)row * N + n0 + (tx << 2)) = o;
        }
    }
}

// ---------------- top-k + H + deg_e ----------------------------------------
__global__ void topk_kernel() {
    int gw = (blockIdx.x * blockDim.x + threadIdx.x) >> 5;
    int lane = threadIdx.x & 31;
    if (gw >= D_ * M_) return;
    int d = gw / M_, i = gw % M_;
    const float* gr = g_gram + (long)d * M_ * M_;
    float gii = gr[(long)i * M_ + i];
    float vals[6];
    #pragma unroll
    for (int q = 0; q < 6; q++) {
        int j = q * 32 + lane;
        float gjj = gr[(long)j * M_ + j];
        float dd = gii + gjj - 2.f * gr[(long)i * M_ + j];
        vals[q] = fmaxf(dd, 0.f);
    }
    unsigned selmask = 0;
    for (int it = 0; it < KTOP; it++) {
        float bv = vals[0]; int bq = 0;
        #pragma unroll
        for (int q = 1; q < 6; q++)
            if (vals[q] < bv) { bv = vals[q]; bq = q; }   // lower j wins ties
        int bj = bq * 32 + lane;
        #pragma unroll
        for (int off = 16; off > 0; off >>= 1) {
            float ov = __shfl_xor_sync(0xffffffffu, bv, off);
            int   oj = __shfl_xor_sync(0xffffffffu, bj, off);
            if (ov < bv || (ov == bv && oj < bj)) { bv = ov; bj = oj; }
        }
        if ((bj & 31) == lane) { vals[bj >> 5] = 3.402823466e38f; selmask |= 1u << (bj >> 5); }
    }
    int u = i / 3;
    float cnt = 0.f;
    float* Hrow = g_H + ((long)d * M_ + i) * M_;
    #pragma unroll
    for (int q = 0; q < 6; q++) {
        int j = q * 32 + lane;
        bool sel = (selmask >> q) & 1u;
        bool cen = (j == u) || (j == u + L_) || (j == u + 2 * L_);
        float h = (sel || cen) ? 1.f : 0.f;
        Hrow[j] = h;
        cnt += h;
    }
    #pragma unroll
    for (int off = 16; off > 0; off >>= 1) cnt += __shfl_xor_sync(0xffffffffu, cnt, off);
    if (lane == 0) g_dege[d * M_ + i] = cnt;
}

__global__ void degv_kernel() {
    int gid = blockIdx.x * blockDim.x + threadIdx.x;
    if (gid >= D_ * M_) return;
    int d = gid / M_, n = gid % M_;
    const float* Hd = g_H + (long)d * M_ * M_;
    float s = 0.f;
    for (int e = 0; e < M_; e++) s += Hd[(long)e * M_ + n];
    g_degv[gid] = s;
}

// ---------------- row normalization ----------------------------------------
__global__ void norm_kernel(const float* __restrict__ outc) {
    int gw = (blockIdx.x * blockDim.x + threadIdx.x) >> 5;
    int lane = threadIdx.x & 31;
    if (gw >= 3 * N_) return;
    int q = gw / N_, r = gw % N_;
    const float* src = outc + (long)r * (3 * G_) + q * G_;
    float vv[8]; float s = 0.f;
    #pragma unroll
    for (int c = 0; c < 8; c++) { vv[c] = src[lane + 32 * c]; s += vv[c] * vv[c]; }
    #pragma unroll
    for (int off = 16; off > 0; off >>= 1) s += __shfl_xor_sync(0xffffffffu, s, off);
    float inv = 1.f / (sqrtf(s) + 1e-8f);
    float* dst = g_xn + ((long)q * N_ + r) * G_;
    #pragma unroll
    for (int c = 0; c < 8; c++) dst[lane + 32 * c] = vv[c] * inv;
}

// ---------------- zero accumulators ----------------------------------------
__global__ void zero_kernel() {
    int tid = blockIdx.x * blockDim.x + threadIdx.x;
    if (tid < 3 * N_) { g_rowsum[tid] = 0.f; g_colsum[tid] = 0.f; }
    if (tid == 0) g_lossacc = 0.f;
}

// ---------------- fused sim tile + exp-sum accumulation --------------------
__global__ __launch_bounds__(256)
void sim_kernel(int px, int py, int pairi) {
    __shared__ float As[16][64];
    __shared__ float Bs[16][64];
    __shared__ float cs_s[64];
    const float* Xm = g_xn + (long)px * N_ * G_;
    const float* Ym = g_xn + (long)py * N_ * G_;
    const int i0 = blockIdx.y * 64;
    const int j0 = blockIdx.x * 64;
    const int tid = threadIdx.x;
    const int tx = tid & 15, ty = tid >> 4;
    float acc[4][4];
    #pragma unroll
    for (int i = 0; i < 4; i++)
        #pragma unroll
        for (int j = 0; j < 4; j++) acc[i][j] = 0.f;

    for (int k0 = 0; k0 < G_; k0 += 16) {
        {
            int m = tid >> 2, k = (tid & 3) << 2;
            float4 t4 = *(const float4*)(Xm + (long)(i0 + m) * G_ + k0 + k);
            As[k+0][m] = t4.x; As[k+1][m] = t4.y; As[k+2][m] = t4.z; As[k+3][m] = t4.w;
        }
        {
            int n = tid >> 2, k = (tid & 3) << 2;
            float4 t4 = *(const float4*)(Ym + (long)(j0 + n) * G_ + k0 + k);
            Bs[k+0][n] = t4.x; Bs[k+1][n] = t4.y; Bs[k+2][n] = t4.z; Bs[k+3][n] = t4.w;
        }
        __syncthreads();
        #pragma unroll
        for (int k = 0; k < 16; k++) {
            float4 av = *(const float4*)&As[k][ty << 2];
            float4 bv = *(const float4*)&Bs[k][tx << 2];
            float aa[4] = {av.x, av.y, av.z, av.w};
            float bb[4] = {bv.x, bv.y, bv.z, bv.w};
            #pragma unroll
            for (int i = 0; i < 4; i++)
                #pragma unroll
                for (int j = 0; j < 4; j++)
                    acc[i][j] = fmaf(aa[i], bb[j], acc[i][j]);
        }
        __syncthreads();
    }

    if (tid < 64) cs_s[tid] = 0.f;
    __syncthreads();
    float rowp[4] = {0.f, 0.f, 0.f, 0.f};
    float colp[4] = {0.f, 0.f, 0.f, 0.f};
    #pragma unroll
    for (int i = 0; i < 4; i++)
        #pragma unroll
        for (int j = 0; j < 4; j++) {
            float e = __expf(acc[i][j] * INV_TAU);
            rowp[i] += e;
            colp[j] += e;
        }
    // row partials: reduce over tx (low 4 lane bits => stays within same ty)
    #pragma unroll
    for (int off = 1; off < 16; off <<= 1)
        #pragma unroll
        for (int i = 0; i < 4; i++)
            rowp[i] += __shfl_xor_sync(0xffffffffu, rowp[i], off);
    if (tx == 0) {
        #pragma unroll
        for (int i = 0; i < 4; i++)
            atomicAdd(&g_rowsum[pairi * N_ + i0 + (ty << 2) + i], rowp[i]);
    }
    #pragma unroll
    for (int j = 0; j < 4; j++) atomicAdd(&cs_s[(tx << 2) + j], colp[j]);
    __syncthreads();
    if (tid < 64) atomicAdd(&g_colsum[pairi * N_ + j0 + tid], cs_s[tid]);
}

// ---------------- diagonal + loss accumulation -----------------------------
__global__ void loss_kernel() {
    int gw = (blockIdx.x * blockDim.x + threadIdx.x) >> 5;
    int lane = threadIdx.x & 31;
    if (gw >= 3 * N_) return;
    int p = gw / N_, i = gw % N_;
    const int pxA[3] = {0, 0, 1};
    const int pyA[3] = {1, 2, 2};
    const float* x = g_xn + ((long)pxA[p] * N_ + i) * G_;
    const float* y = g_xn + ((long)pyA[p] * N_ + i) * G_;
    float dot = 0.f;
    #pragma unroll
    for (int c = 0; c < 8; c++) dot += x[lane + 32 * c] * y[lane + 32 * c];
    #pragma unroll
    for (int off = 16; off > 0; off >>= 1) dot += __shfl_xor_sync(0xffffffffu, dot, off);
    if (lane == 0) {
        float ci = 2.f * dot * INV_TAU - logf(g_rowsum[p * N_ + i]) - logf(g_colsum[p * N_ + i]);
        atomicAdd(&g_lossacc, ci);
    }
}

__global__ void finish_kernel(float* out, int idx) {
    if (threadIdx.x == 0 && blockIdx.x == 0)
        out[idx] = -g_lossacc / (float)(2 * N_ * 3);
}

// ---------------- launch ----------------------------------------------------
extern "C" void kernel_launch(void* const* d_in, const int* in_sizes, int n_in,
                              void* d_out, int out_size) {
    const float* t   = (const float*)d_in[0];
    const float* a   = (const float*)d_in[1];
    const float* v   = (const float*)d_in[2];
    const float* Wfc = (const float*)d_in[3];
    const float* bfc = (const float*)d_in[4];
    const float* Wh  = (const float*)d_in[5];
    const float* bh  = (const float*)d_in[6];
    float* out = (float*)d_out;

    void *pf, *pg, *ph, *pde, *pdv, *px, *pe, *py;
    cudaGetSymbolAddress(&pf,  g_feat);
    cudaGetSymbolAddress(&pg,  g_gram);
    cudaGetSymbolAddress(&ph,  g_H);
    cudaGetSymbolAddress(&pde, g_dege);
    cudaGetSymbolAddress(&pdv, g_degv);
    cudaGetSymbolAddress(&px,  g_X);
    cudaGetSymbolAddress(&pe,  g_E);
    cudaGetSymbolAddress(&py,  g_Y);
    float* feat = (float*)pf;  float* gram = (float*)pg;  float* H = (float*)ph;
    float* dege = (float*)pde; float* degv = (float*)pdv;
    float* X = (float*)px;     float* E = (float*)pe;     float* Y = (float*)py;

    pack_kernel<<<6144, 256>>>(t, a, v);
    zero_kernel<<<48, 256>>>();

    // gram[d] = feat_d @ feat_d^T   (192x192x512, batched)
    gemm_k<0,1,0><<<dim3(3,3,D_), 256>>>(feat, feat, gram,
        M_, M_, DIM_, DIM_, DIM_,
        (long)M_*DIM_, (long)M_*DIM_, (long)M_*M_, nullptr, nullptr, nullptr);

    topk_kernel<<<1536, 256>>>();
    degv_kernel<<<48, 256>>>();

    // X = feat @ W_fc + b_fc   (12288x256x512)
    gemm_k<0,0,1><<<dim3(4,192,1), 256>>>(feat, Wfc, X,
        D_*M_, G_, DIM_, DIM_, G_, 0, 0, 0, bfc, nullptr, nullptr);

    // E = (H @ X) / deg_e   (batched 192x256x192)
    gemm_k<0,0,2><<<dim3(4,3,D_), 256>>>(H, X, E,
        M_, G_, M_, M_, G_,
        (long)M_*M_, (long)M_*G_, (long)M_*G_, nullptr, dege, nullptr);

    // Y = (H^T @ E) / deg_v
    gemm_k<1,0,2><<<dim3(4,3,D_), 256>>>(H, E, Y,
        M_, G_, M_, M_, G_,
        (long)M_*M_, (long)M_*G_, (long)M_*G_, nullptr, degv, nullptr);

    // out = relu(Y @ W_h + b_h), remapped into out_cat layout in d_out
    gemm_k<0,0,3><<<dim3(4,192,1), 256>>>(Y, Wh, nullptr,
        D_*M_, G_, G_, G_, G_, 0, 0, 0, bh, nullptr, out);

    norm_kernel<<<1536, 256>>>(out);

    sim_kernel<<<dim3(64,64), 256>>>(0, 1, 0);   // (tn, an)
    sim_kernel<<<dim3(64,64), 256>>>(0, 2, 1);   // (tn, vn)
    sim_kernel<<<dim3(64,64), 256>>>(1, 2, 2);   // (an, vn)

    loss_kernel<<<1536, 256>>>();
    finish_kernel<<<1, 32>>>(out, out_size - 1);
}

// round 3
// speedup vs baseline: 3.4285x; 3.4285x over previous
#include <cuda_runtime.h>
#include <cuda_bf16.h>
#include <math.h>

// Problem constants
#define D_    64
#define L_    64
#define M_    192          // 3*L nodes per dialogue
#define DIM_  512
#define G_    256
#define N_    4096         // D*L
#define KTOP  12           // int(64*0.2)
#define INV_TAU (1.0f/0.07f)

// ---------------- scratch (static __device__ arrays: allocation-free) ------
__device__ float g_feat[D_*M_*DIM_];   // [d, jm, f]
__device__ float g_gram[D_*M_*M_];     // per-dialogue gram
__device__ float g_H[D_*M_*M_];        // incidence (0/1)
__device__ float g_dege[D_*M_];
__device__ float g_degv[D_*M_];
__device__ float g_X[D_*M_*G_];
__device__ float g_E[D_*M_*G_];
__device__ float g_Y[D_*M_*G_];
__device__ float g_xn[3*N_*G_];        // normalized tn/an/vn (fp32, for loss diag)
__device__ __nv_bfloat16 g_xnh[3*N_*G_];  // bf16 copy for tensor-core sims
__device__ float g_rowsum[3*N_];
__device__ float g_colsum[3*N_];
__device__ float g_lossacc;

// ---------------- feat packing ---------------------------------------------
__global__ void pack_kernel(const float* __restrict__ t,
                            const float* __restrict__ a,
                            const float* __restrict__ v) {
    int gid = blockIdx.x * 256 + threadIdx.x;   // float4 index, 12288*128 total
    int row = gid >> 7;
    int c   = gid & 127;
    int d   = row / M_;
    int jm  = row % M_;
    const float* src = (jm < L_) ? t : (jm < 2*L_) ? a : v;
    int srow = d * L_ + (jm & 63);
    float4 val = ((const float4*)src)[(long)srow * 128 + c];
    ((float4*)g_feat)[(long)row * 128 + c] = val;
}

// ---------------- generic tiled GEMM ---------------------------------------
// TA: 0 => A[m*lda+k], 1 => A[k*lda+m].  TB: 0 => B[k*ldb+n], 1 => B[n*ldb+k]
// EPI: 0 plain, 1 +bias, 2 /divrow[b*M+row], 3 +bias,relu,remap->out_cat
template<int TA, int TB, int EPI>
__global__ __launch_bounds__(256)
void gemm_k(const float* __restrict__ Ag, const float* __restrict__ Bg,
            float* __restrict__ Cg,
            int M, int N, int K, int lda, int ldb,
            long sA, long sB, long sC,
            const float* __restrict__ bias,
            const float* __restrict__ divrow,
            float* __restrict__ outp) {
    __shared__ float As[16][64];
    __shared__ float Bs[16][64];
    const int b = blockIdx.z;
    const float* A = Ag + (long)b * sA;
    const float* B = Bg + (long)b * sB;
    const int m0 = blockIdx.y * 64;
    const int n0 = blockIdx.x * 64;
    const int tid = threadIdx.x;
    const int tx = tid & 15, ty = tid >> 4;
    float acc[4][4];
    #pragma unroll
    for (int i = 0; i < 4; i++)
        #pragma unroll
        for (int j = 0; j < 4; j++) acc[i][j] = 0.f;

    for (int k0 = 0; k0 < K; k0 += 16) {
        if (TA == 0) {
            int m = tid >> 2, k = (tid & 3) << 2;
            float4 t4 = *(const float4*)(A + (long)(m0 + m) * lda + k0 + k);
            As[k+0][m] = t4.x; As[k+1][m] = t4.y; As[k+2][m] = t4.z; As[k+3][m] = t4.w;
        } else {
            int k = tid >> 4, m = (tid & 15) << 2;
            *(float4*)&As[k][m] = *(const float4*)(A + (long)(k0 + k) * lda + m0 + m);
        }
        if (TB == 0) {
            int k = tid >> 4, n = (tid & 15) << 2;
            *(float4*)&Bs[k][n] = *(const float4*)(B + (long)(k0 + k) * ldb + n0 + n);
        } else {
            int n = tid >> 2, k = (tid & 3) << 2;
            float4 t4 = *(const float4*)(B + (long)(n0 + n) * ldb + k0 + k);
            Bs[k+0][n] = t4.x; Bs[k+1][n] = t4.y; Bs[k+2][n] = t4.z; Bs[k+3][n] = t4.w;
        }
        __syncthreads();
        #pragma unroll
        for (int k = 0; k < 16; k++) {
            float4 av = *(const float4*)&As[k][ty << 2];
            float4 bv = *(const float4*)&Bs[k][tx << 2];
            float aa[4] = {av.x, av.y, av.z, av.w};
            float bb[4] = {bv.x, bv.y, bv.z, bv.w};
            #pragma unroll
            for (int i = 0; i < 4; i++)
                #pragma unroll
                for (int j = 0; j < 4; j++)
                    acc[i][j] = fmaf(aa[i], bb[j], acc[i][j]);
        }
        __syncthreads();
    }

    #pragma unroll
    for (int i = 0; i < 4; i++) {
        int row = m0 + (ty << 2) + i;
        float dr = 1.f;
        if (EPI == 2) dr = divrow[(long)b * M + row];
        float vals[4];
        #pragma unroll
        for (int j = 0; j < 4; j++) {
            int col = n0 + (tx << 2) + j;
            float x = acc[i][j];
            if (EPI == 1 || EPI == 3) x += bias[col];
            if (EPI == 2) x = x / dr;
            if (EPI == 3) x = fmaxf(x, 0.f);
            vals[j] = x;
        }
        float4 o = make_float4(vals[0], vals[1], vals[2], vals[3]);
        if (EPI == 3) {
            int d = row / M_, jm = row % M_;
            long base = ((long)(d * L_ + (jm & 63)) * (3 * G_)) + (jm >> 6) * G_ + n0 + (tx << 2);
            *(float4*)(outp + base) = o;
        } else {
            float* Cb = Cg + (long)b * sC;
            *(float4*)(Cb + (long)row * N + n0 + (tx << 2)) = o;
        }
    }
}

// ---------------- top-k + H + deg_e ----------------------------------------
__global__ void topk_kernel() {
    int gw = (blockIdx.x * blockDim.x + threadIdx.x) >> 5;
    int lane = threadIdx.x & 31;
    if (gw >= D_ * M_) return;
    int d = gw / M_, i = gw % M_;
    const float* gr = g_gram + (long)d * M_ * M_;
    float gii = gr[(long)i * M_ + i];
    float vals[6];
    #pragma unroll
    for (int q = 0; q < 6; q++) {
        int j = q * 32 + lane;
        float gjj = gr[(long)j * M_ + j];
        float dd = gii + gjj - 2.f * gr[(long)i * M_ + j];
        vals[q] = fmaxf(dd, 0.f);
    }
    unsigned selmask = 0;
    for (int it = 0; it < KTOP; it++) {
        float bv = vals[0]; int bq = 0;
        #pragma unroll
        for (int q = 1; q < 6; q++)
            if (vals[q] < bv) { bv = vals[q]; bq = q; }   // lower j wins ties
        int bj = bq * 32 + lane;
        #pragma unroll
        for (int off = 16; off > 0; off >>= 1) {
            float ov = __shfl_xor_sync(0xffffffffu, bv, off);
            int   oj = __shfl_xor_sync(0xffffffffu, bj, off);
            if (ov < bv || (ov == bv && oj < bj)) { bv = ov; bj = oj; }
        }
        if ((bj & 31) == lane) { vals[bj >> 5] = 3.402823466e38f; selmask |= 1u << (bj >> 5); }
    }
    int u = i / 3;
    float cnt = 0.f;
    float* Hrow = g_H + ((long)d * M_ + i) * M_;
    #pragma unroll
    for (int q = 0; q < 6; q++) {
        int j = q * 32 + lane;
        bool sel = (selmask >> q) & 1u;
        bool cen = (j == u) || (j == u + L_) || (j == u + 2 * L_);
        float h = (sel || cen) ? 1.f : 0.f;
        Hrow[j] = h;
        cnt += h;
    }
    #pragma unroll
    for (int off = 16; off > 0; off >>= 1) cnt += __shfl_xor_sync(0xffffffffu, cnt, off);
    if (lane == 0) g_dege[d * M_ + i] = cnt;
}

__global__ void degv_kernel() {
    int gid = blockIdx.x * blockDim.x + threadIdx.x;
    if (gid >= D_ * M_) return;
    int d = gid / M_, n = gid % M_;
    const float* Hd = g_H + (long)d * M_ * M_;
    float s = 0.f;
    for (int e = 0; e < M_; e++) s += Hd[(long)e * M_ + n];
    g_degv[gid] = s;
}

// ---------------- row normalization (fp32 + bf16 outputs) -------------------
__global__ void norm_kernel(const float* __restrict__ outc) {
    int gw = (blockIdx.x * blockDim.x + threadIdx.x) >> 5;
    int lane = threadIdx.x & 31;
    if (gw >= 3 * N_) return;
    int q = gw / N_, r = gw % N_;
    const float* src = outc + (long)r * (3 * G_) + q * G_;
    float vv[8]; float s = 0.f;
    #pragma unroll
    for (int c = 0; c < 8; c++) { vv[c] = src[lane + 32 * c]; s += vv[c] * vv[c]; }
    #pragma unroll
    for (int off = 16; off > 0; off >>= 1) s += __shfl_xor_sync(0xffffffffu, s, off);
    float inv = 1.f / (sqrtf(s) + 1e-8f);
    float* dst = g_xn + ((long)q * N_ + r) * G_;
    __nv_bfloat16* dsth = g_xnh + ((long)q * N_ + r) * G_;
    #pragma unroll
    for (int c = 0; c < 8; c++) {
        float x = vv[c] * inv;
        dst[lane + 32 * c] = x;
        dsth[lane + 32 * c] = __float2bfloat16(x);
    }
}

// ---------------- zero accumulators ----------------------------------------
__global__ void zero_kernel() {
    int tid = blockIdx.x * blockDim.x + threadIdx.x;
    if (tid < 3 * N_) { g_rowsum[tid] = 0.f; g_colsum[tid] = 0.f; }
    if (tid == 0) g_lossacc = 0.f;
}

// ---------------- tensor-core sim + fused exp row/col sums ------------------
__device__ __forceinline__ void mma16816(float* c, const unsigned* a,
                                         unsigned b0, unsigned b1) {
    asm volatile(
        "mma.sync.aligned.m16n8k16.row.col.f32.bf16.bf16.f32 "
        "{%0,%1,%2,%3},{%4,%5,%6,%7},{%8,%9},{%0,%1,%2,%3};"
        : "+f"(c[0]), "+f"(c[1]), "+f"(c[2]), "+f"(c[3])
        : "r"(a[0]), "r"(a[1]), "r"(a[2]), "r"(a[3]), "r"(b0), "r"(b1));
}

#define STR 40   // shared row stride in halves (32 data + 8 pad) -> conflict-free

__global__ __launch_bounds__(256)
void sim_mma_kernel() {
    const int pxA[3] = {0, 0, 1};
    const int pyA[3] = {1, 2, 2};
    const int pair = blockIdx.z;
    const __nv_bfloat16* Xm = g_xnh + (long)pxA[pair] * N_ * G_;
    const __nv_bfloat16* Ym = g_xnh + (long)pyA[pair] * N_ * G_;
    const int i0 = blockIdx.y * 128;
    const int j0 = blockIdx.x * 128;

    __shared__ __nv_bfloat16 As[128 * STR];
    __shared__ __nv_bfloat16 Bs[128 * STR];
    __shared__ float sRow[128];
    __shared__ float sCol[128];

    const int tid = threadIdx.x;
    const int lane = tid & 31;
    const int wid = tid >> 5;
    const int wm = wid >> 1;        // 0..3 -> 32-row strip
    const int wn = wid & 1;         // 0..1 -> 64-col strip
    const int g = lane >> 2;
    const int c2 = (lane & 3) << 1;

    if (tid < 128) { sRow[tid] = 0.f; sCol[tid] = 0.f; }

    float acc[2][8][4];
    #pragma unroll
    for (int mi = 0; mi < 2; mi++)
        #pragma unroll
        for (int ni = 0; ni < 8; ni++)
            #pragma unroll
            for (int r = 0; r < 4; r++) acc[mi][ni][r] = 0.f;

    for (int k0 = 0; k0 < G_; k0 += 32) {
        #pragma unroll
        for (int q = 0; q < 2; q++) {
            int qq = tid * 2 + q;           // 0..511
            int row = qq >> 2, kc = qq & 3; // 128 rows x 4 chunks of 8 halves
            *(uint4*)&As[row * STR + kc * 8] =
                *(const uint4*)(Xm + (long)(i0 + row) * G_ + k0 + kc * 8);
            *(uint4*)&Bs[row * STR + kc * 8] =
                *(const uint4*)(Ym + (long)(j0 + row) * G_ + k0 + kc * 8);
        }
        __syncthreads();
        #pragma unroll
        for (int kk = 0; kk < 32; kk += 16) {
            unsigned a[2][4];
            #pragma unroll
            for (int mi = 0; mi < 2; mi++) {
                int am = wm * 32 + mi * 16;
                a[mi][0] = *(const unsigned*)&As[(am + g)     * STR + kk + c2];
                a[mi][1] = *(const unsigned*)&As[(am + 8 + g) * STR + kk + c2];
                a[mi][2] = *(const unsigned*)&As[(am + g)     * STR + kk + 8 + c2];
                a[mi][3] = *(const unsigned*)&As[(am + 8 + g) * STR + kk + 8 + c2];
            }
            #pragma unroll
            for (int ni = 0; ni < 8; ni++) {
                int bn = wn * 64 + ni * 8;
                unsigned b0 = *(const unsigned*)&Bs[(bn + g) * STR + kk + c2];
                unsigned b1 = *(const unsigned*)&Bs[(bn + g) * STR + kk + 8 + c2];
                mma16816(acc[0][ni], a[0], b0, b1);
                mma16816(acc[1][ni], a[1], b0, b1);
            }
        }
        __syncthreads();
    }

    // exp(sim/tau)
    float e[2][8][4];
    #pragma unroll
    for (int mi = 0; mi < 2; mi++)
        #pragma unroll
        for (int ni = 0; ni < 8; ni++)
            #pragma unroll
            for (int r = 0; r < 4; r++)
                e[mi][ni][r] = __expf(acc[mi][ni][r] * INV_TAU);

    // row partial sums: C frag rows = {g, g+8}; reduce over lane&3 (cols)
    #pragma unroll
    for (int mi = 0; mi < 2; mi++)
        #pragma unroll
        for (int h = 0; h < 2; h++) {
            float s = 0.f;
            #pragma unroll
            for (int ni = 0; ni < 8; ni++)
                s += h ? (e[mi][ni][2] + e[mi][ni][3])
                       : (e[mi][ni][0] + e[mi][ni][1]);
            s += __shfl_xor_sync(0xffffffffu, s, 1);
            s += __shfl_xor_sync(0xffffffffu, s, 2);
            if ((lane & 3) == 0)
                atomicAdd(&sRow[wm * 32 + mi * 16 + h * 8 + g], s);
        }

    // col partial sums: C frag cols = 2*(lane&3)+p; reduce over lane>>2 (rows)
    #pragma unroll
    for (int ni = 0; ni < 8; ni++)
        #pragma unroll
        for (int p = 0; p < 2; p++) {
            float s = e[0][ni][p] + e[0][ni][p + 2] + e[1][ni][p] + e[1][ni][p + 2];
            s += __shfl_xor_sync(0xffffffffu, s, 4);
            s += __shfl_xor_sync(0xffffffffu, s, 8);
            s += __shfl_xor_sync(0xffffffffu, s, 16);
            if (lane < 4)
                atomicAdd(&sCol[wn * 64 + ni * 8 + lane * 2 + p], s);
        }

    __syncthreads();
    if (tid < 128) {
        atomicAdd(&g_rowsum[pair * N_ + i0 + tid], sRow[tid]);
        atomicAdd(&g_colsum[pair * N_ + j0 + tid], sCol[tid]);
    }
}

// ---------------- diagonal + loss accumulation -----------------------------
__global__ void loss_kernel() {
    int gw = (blockIdx.x * blockDim.x + threadIdx.x) >> 5;
    int lane = threadIdx.x & 31;
    if (gw >= 3 * N_) return;
    int p = gw / N_, i = gw % N_;
    const int pxA[3] = {0, 0, 1};
    const int pyA[3] = {1, 2, 2};
    const float* x = g_xn + ((long)pxA[p] * N_ + i) * G_;
    const float* y = g_xn + ((long)pyA[p] * N_ + i) * G_;
    float dot = 0.f;
    #pragma unroll
    for (int c = 0; c < 8; c++) dot += x[lane + 32 * c] * y[lane + 32 * c];
    #pragma unroll
    for (int off = 16; off > 0; off >>= 1) dot += __shfl_xor_sync(0xffffffffu, dot, off);
    if (lane == 0) {
        float ci = 2.f * dot * INV_TAU - logf(g_rowsum[p * N_ + i]) - logf(g_colsum[p * N_ + i]);
        atomicAdd(&g_lossacc, ci);
    }
}

__global__ void finish_kernel(float* out, int idx) {
    if (threadIdx.x == 0 && blockIdx.x == 0)
        out[idx] = -g_lossacc / (float)(2 * N_ * 3);
}

// ---------------- launch ----------------------------------------------------
extern "C" void kernel_launch(void* const* d_in, const int* in_sizes, int n_in,
                              void* d_out, int out_size) {
    const float* t   = (const float*)d_in[0];
    const float* a   = (const float*)d_in[1];
    const float* v   = (const float*)d_in[2];
    const float* Wfc = (const float*)d_in[3];
    const float* bfc = (const float*)d_in[4];
    const float* Wh  = (const float*)d_in[5];
    const float* bh  = (const float*)d_in[6];
    float* out = (float*)d_out;

    void *pf, *pg, *ph, *pde, *pdv, *px, *pe, *py;
    cudaGetSymbolAddress(&pf,  g_feat);
    cudaGetSymbolAddress(&pg,  g_gram);
    cudaGetSymbolAddress(&ph,  g_H);
    cudaGetSymbolAddress(&pde, g_dege);
    cudaGetSymbolAddress(&pdv, g_degv);
    cudaGetSymbolAddress(&px,  g_X);
    cudaGetSymbolAddress(&pe,  g_E);
    cudaGetSymbolAddress(&py,  g_Y);
    float* feat = (float*)pf;  float* gram = (float*)pg;  float* H = (float*)ph;
    float* dege = (float*)pde; float* degv = (float*)pdv;
    float* X = (float*)px;     float* E = (float*)pe;     float* Y = (float*)py;

    pack_kernel<<<6144, 256>>>(t, a, v);
    zero_kernel<<<48, 256>>>();

    // gram[d] = feat_d @ feat_d^T   (192x192x512, batched)
    gemm_k<0,1,0><<<dim3(3,3,D_), 256>>>(feat, feat, gram,
        M_, M_, DIM_, DIM_, DIM_,
        (long)M_*DIM_, (long)M_*DIM_, (long)M_*M_, nullptr, nullptr, nullptr);

    topk_kernel<<<1536, 256>>>();
    degv_kernel<<<48, 256>>>();

    // X = feat @ W_fc + b_fc   (12288x256x512)
    gemm_k<0,0,1><<<dim3(4,192,1), 256>>>(feat, Wfc, X,
        D_*M_, G_, DIM_, DIM_, G_, 0, 0, 0, bfc, nullptr, nullptr);

    // E = (H @ X) / deg_e   (batched 192x256x192)
    gemm_k<0,0,2><<<dim3(4,3,D_), 256>>>(H, X, E,
        M_, G_, M_, M_, G_,
        (long)M_*M_, (long)M_*G_, (long)M_*G_, nullptr, dege, nullptr);

    // Y = (H^T @ E) / deg_v
    gemm_k<1,0,2><<<dim3(4,3,D_), 256>>>(H, E, Y,
        M_, G_, M_, M_, G_,
        (long)M_*M_, (long)M_*G_, (long)M_*G_, nullptr, degv, nullptr);

    // out = relu(Y @ W_h + b_h), remapped into out_cat layout in d_out
    gemm_k<0,0,3><<<dim3(4,192,1), 256>>>(Y, Wh, nullptr,
        D_*M_, G_, G_, G_, G_, 0, 0, 0, bh, nullptr, out);

    norm_kernel<<<1536, 256>>>(out);

    // all three contrastive sims on tensor cores, fused exp/row/col sums
    sim_mma_kernel<<<dim3(32, 32, 3), 256>>>();

    loss_kernel<<<1536, 256>>>();
    finish_kernel<<<1, 32>>>(out, out_size - 1);
}

// round 5
// speedup vs baseline: 4.9501x; 1.4438x over previous
#include <cuda_runtime.h>
#include <cuda_bf16.h>
#include <math.h>

// Problem constants
#define D_    64
#define L_    64
#define M_    192          // 3*L nodes per dialogue
#define DIM_  512
#define G_    256
#define N_    4096         // D*L
#define KTOP  12           // int(64*0.2)
#define INV_TAU (1.0f/0.07f)

// ---------------- scratch (static __device__ arrays: allocation-free) ------
__device__ float g_feat[D_*M_*DIM_];   // [d, jm, f]
__device__ float g_gram[D_*M_*M_];     // per-dialogue gram
__device__ float g_H[D_*M_*M_];        // incidence (0/1), [d][e][n]
__device__ float g_Ht[D_*M_*M_];       // transpose [d][n][e]
__device__ float g_dege[D_*M_];
__device__ float g_degv[D_*M_];
__device__ float g_X[D_*M_*G_];
__device__ float g_E[D_*M_*G_];
__device__ float g_Y[D_*M_*G_];
__device__ float g_xn[3*N_*G_];        // normalized tn/an/vn (fp32, for loss diag)
__device__ __nv_bfloat16 g_xnh[3*N_*G_];  // bf16 copy for tensor-core sims
__device__ float g_rowsum[3*N_];
__device__ float g_colsum[3*N_];
__device__ float g_lossacc;

// ---------------- tf32 helpers ---------------------------------------------
__device__ __forceinline__ unsigned f2tf(float x) {
    unsigned u;
    asm("cvt.rna.tf32.f32 %0, %1;" : "=r"(u) : "f"(x));
    return u;
}

__device__ __forceinline__ void mma_tf32(float* c, const unsigned* a,
                                         unsigned b0, unsigned b1) {
    asm volatile(
        "mma.sync.aligned.m16n8k8.row.col.f32.tf32.tf32.f32 "
        "{%0,%1,%2,%3},{%4,%5,%6,%7},{%8,%9},{%0,%1,%2,%3};"
        : "+f"(c[0]), "+f"(c[1]), "+f"(c[2]), "+f"(c[3])
        : "r"(a[0]), "r"(a[1]), "r"(a[2]), "r"(a[3]), "r"(b0), "r"(b1));
}

// ---------------- feat packing ---------------------------------------------
__global__ void pack_kernel(const float* __restrict__ t,
                            const float* __restrict__ a,
                            const float* __restrict__ v) {
    int gid = blockIdx.x * 256 + threadIdx.x;   // float4 index, 12288*128 total
    int row = gid >> 7;
    int c   = gid & 127;
    int d   = row / M_;
    int jm  = row % M_;
    const float* src = (jm < L_) ? t : (jm < 2*L_) ? a : v;
    int srow = d * L_ + (jm & 63);
    float4 val = ((const float4*)src)[(long)srow * 128 + c];
    ((float4*)g_feat)[(long)row * 128 + c] = val;
}

// ---------------- 3x-tf32 batched gram: gram[d] = feat_d @ feat_d^T ---------
__global__ __launch_bounds__(128)
void gram_tc() {
    __shared__ unsigned Ah[64*36], Al[64*36], Bh[64*36], Bl[64*36];
    const int d = blockIdx.z;
    const float* F = g_feat + (long)d * M_ * DIM_;
    const int m0 = blockIdx.y * 64, n0 = blockIdx.x * 64;
    const int tid = threadIdx.x, lane = tid & 31, wid = tid >> 5;
    const int wm = (wid >> 1) * 32, wn = (wid & 1) * 32;
    const int g = lane >> 2, c = lane & 3;
    float acc[2][4][4];
    #pragma unroll
    for (int mi = 0; mi < 2; mi++)
        #pragma unroll
        for (int ni = 0; ni < 4; ni++)
            #pragma unroll
            for (int r = 0; r < 4; r++) acc[mi][ni][r] = 0.f;

    for (int k0 = 0; k0 < DIM_; k0 += 32) {
        #pragma unroll
        for (int it = 0; it < 4; it++) {
            int idx = it * 128 + tid;
            int m = idx >> 3, kc = (idx & 7) << 2;
            float4 t4 = *(const float4*)(F + (long)(m0 + m) * DIM_ + k0 + kc);
            float xs[4] = {t4.x, t4.y, t4.z, t4.w};
            #pragma unroll
            for (int j = 0; j < 4; j++) {
                unsigned h = f2tf(xs[j]);
                Ah[m*36 + kc + j] = h;
                Al[m*36 + kc + j] = f2tf(xs[j] - __uint_as_float(h));
            }
            float4 u4 = *(const float4*)(F + (long)(n0 + m) * DIM_ + k0 + kc);
            float ys[4] = {u4.x, u4.y, u4.z, u4.w};
            #pragma unroll
            for (int j = 0; j < 4; j++) {
                unsigned h = f2tf(ys[j]);
                Bh[m*36 + kc + j] = h;
                Bl[m*36 + kc + j] = f2tf(ys[j] - __uint_as_float(h));
            }
        }
        __syncthreads();
        #pragma unroll
        for (int kk = 0; kk < 32; kk += 8) {
            unsigned ah[2][4], al[2][4];
            #pragma unroll
            for (int mi = 0; mi < 2; mi++) {
                int rb = wm + mi * 16;
                ah[mi][0] = Ah[(rb+g)*36 + kk+c];   al[mi][0] = Al[(rb+g)*36 + kk+c];
                ah[mi][1] = Ah[(rb+8+g)*36 + kk+c]; al[mi][1] = Al[(rb+8+g)*36 + kk+c];
                ah[mi][2] = Ah[(rb+g)*36 + kk+c+4]; al[mi][2] = Al[(rb+g)*36 + kk+c+4];
                ah[mi][3] = Ah[(rb+8+g)*36 + kk+c+4]; al[mi][3] = Al[(rb+8+g)*36 + kk+c+4];
            }
            #pragma unroll
            for (int ni = 0; ni < 4; ni++) {
                int cb = wn + ni * 8 + g;
                unsigned bh0 = Bh[cb*36 + kk+c], bh1 = Bh[cb*36 + kk+c+4];
                unsigned bl0 = Bl[cb*36 + kk+c], bl1 = Bl[cb*36 + kk+c+4];
                #pragma unroll
                for (int mi = 0; mi < 2; mi++) {
                    mma_tf32(acc[mi][ni], ah[mi], bh0, bh1);
                    mma_tf32(acc[mi][ni], ah[mi], bl0, bl1);
                    mma_tf32(acc[mi][ni], al[mi], bh0, bh1);
                }
            }
        }
        __syncthreads();
    }
    float* C = g_gram + (long)d * M_ * M_;
    #pragma unroll
    for (int mi = 0; mi < 2; mi++)
        #pragma unroll
        for (int h = 0; h < 2; h++) {
            int row = m0 + wm + mi * 16 + h * 8 + g;
            #pragma unroll
            for (int ni = 0; ni < 4; ni++) {
                int col = n0 + wn + ni * 8 + 2 * c;
                float2 o = make_float2(acc[mi][ni][h*2+0], acc[mi][ni][h*2+1]);
                *(float2*)(C + (long)row * M_ + col) = o;
            }
        }
}

// ---------------- generic tf32 tensor-core GEMM ------------------------------
// C = A(row-major m×k) @ B(row-major k×n).
// EPI: 0 plain, 1 +bias, 2 /divrow[b*M+row], 3 +bias,relu,remap->out_cat
template<int EPI>
__global__ __launch_bounds__(128)
void gemm_tc(const float* __restrict__ Ag, const float* __restrict__ Bg,
             float* __restrict__ Cg,
             int M, int N, int K, int lda, int ldb,
             long sA, long sB, long sC,
             const float* __restrict__ bias,
             const float* __restrict__ divrow,
             float* __restrict__ outp) {
    __shared__ unsigned As[64*36];
    __shared__ unsigned Bs[32*72];
    const int b = blockIdx.z;
    const float* A = Ag + (long)b * sA;
    const float* B = Bg + (long)b * sB;
    const int m0 = blockIdx.y * 64, n0 = blockIdx.x * 64;
    const int tid = threadIdx.x, lane = tid & 31, wid = tid >> 5;
    const int wm = (wid >> 1) * 32, wn = (wid & 1) * 32;
    const int g = lane >> 2, c = lane & 3;
    float acc[2][4][4];
    #pragma unroll
    for (int mi = 0; mi < 2; mi++)
        #pragma unroll
        for (int ni = 0; ni < 4; ni++)
            #pragma unroll
            for (int r = 0; r < 4; r++) acc[mi][ni][r] = 0.f;

    for (int k0 = 0; k0 < K; k0 += 32) {
        #pragma unroll
        for (int it = 0; it < 4; it++) {
            int idx = it * 128 + tid;
            int m = idx >> 3, kc = (idx & 7) << 2;
            float4 t4 = *(const float4*)(A + (long)(m0 + m) * lda + k0 + kc);
            unsigned* p = &As[m*36 + kc];
            p[0] = f2tf(t4.x); p[1] = f2tf(t4.y); p[2] = f2tf(t4.z); p[3] = f2tf(t4.w);
            int k = idx >> 4, nc = (idx & 15) << 2;
            float4 u4 = *(const float4*)(B + (long)(k0 + k) * ldb + n0 + nc);
            unsigned* q = &Bs[k*72 + nc];
            q[0] = f2tf(u4.x); q[1] = f2tf(u4.y); q[2] = f2tf(u4.z); q[3] = f2tf(u4.w);
        }
        __syncthreads();
        #pragma unroll
        for (int kk = 0; kk < 32; kk += 8) {
            unsigned a[2][4];
            #pragma unroll
            for (int mi = 0; mi < 2; mi++) {
                int rb = wm + mi * 16;
                a[mi][0] = As[(rb+g)*36 + kk+c];
                a[mi][1] = As[(rb+8+g)*36 + kk+c];
                a[mi][2] = As[(rb+g)*36 + kk+c+4];
                a[mi][3] = As[(rb+8+g)*36 + kk+c+4];
            }
            #pragma unroll
            for (int ni = 0; ni < 4; ni++) {
                int cb = wn + ni * 8 + g;
                unsigned b0 = Bs[(kk+c)*72 + cb];
                unsigned b1 = Bs[(kk+c+4)*72 + cb];
                mma_tf32(acc[0][ni], a[0], b0, b1);
                mma_tf32(acc[1][ni], a[1], b0, b1);
            }
        }
        __syncthreads();
    }

    #pragma unroll
    for (int mi = 0; mi < 2; mi++)
        #pragma unroll
        for (int h = 0; h < 2; h++) {
            int row = m0 + wm + mi * 16 + h * 8 + g;
            float dr = 1.f;
            if (EPI == 2) dr = divrow[(long)b * M + row];
            #pragma unroll
            for (int ni = 0; ni < 4; ni++) {
                int col = n0 + wn + ni * 8 + 2 * c;
                float x0 = acc[mi][ni][h*2+0];
                float x1 = acc[mi][ni][h*2+1];
                if (EPI == 1 || EPI == 3) {
                    float2 bb = *(const float2*)(bias + col);
                    x0 += bb.x; x1 += bb.y;
                }
                if (EPI == 2) { x0 /= dr; x1 /= dr; }
                if (EPI == 3) { x0 = fmaxf(x0, 0.f); x1 = fmaxf(x1, 0.f); }
                float2 o = make_float2(x0, x1);
                if (EPI == 3) {
                    int d = row / M_, jm = row % M_;
                    long base = ((long)(d * L_ + (jm & 63)) * (3 * G_)) + (jm >> 6) * G_ + col;
                    *(float2*)(outp + base) = o;
                } else {
                    float* Cb = Cg + (long)b * sC;
                    *(float2*)(Cb + (long)row * N + col) = o;
                }
            }
        }
}

// ---------------- top-k + H + Ht + deg_e ------------------------------------
__global__ void topk_kernel() {
    int gw = (blockIdx.x * blockDim.x + threadIdx.x) >> 5;
    int lane = threadIdx.x & 31;
    if (gw >= D_ * M_) return;
    int d = gw / M_, i = gw % M_;
    const float* gr = g_gram + (long)d * M_ * M_;
    float gii = gr[(long)i * M_ + i];
    float vals[6];
    #pragma unroll
    for (int q = 0; q < 6; q++) {
        int j = q * 32 + lane;
        float gjj = gr[(long)j * M_ + j];
        float dd = gii + gjj - 2.f * gr[(long)i * M_ + j];
        vals[q] = fmaxf(dd, 0.f);
    }
    unsigned selmask = 0;
    for (int it = 0; it < KTOP; it++) {
        float bv = vals[0]; int bq = 0;
        #pragma unroll
        for (int q = 1; q < 6; q++)
            if (vals[q] < bv) { bv = vals[q]; bq = q; }   // lower j wins ties
        int bj = bq * 32 + lane;
        #pragma unroll
        for (int off = 16; off > 0; off >>= 1) {
            float ov = __shfl_xor_sync(0xffffffffu, bv, off);
            int   oj = __shfl_xor_sync(0xffffffffu, bj, off);
            if (ov < bv || (ov == bv && oj < bj)) { bv = ov; bj = oj; }
        }
        if ((bj & 31) == lane) { vals[bj >> 5] = 3.402823466e38f; selmask |= 1u << (bj >> 5); }
    }
    int u = i / 3;
    float cnt = 0.f;
    float* Hrow = g_H + ((long)d * M_ + i) * M_;
    float* Htb  = g_Ht + (long)d * M_ * M_;
    #pragma unroll
    for (int q = 0; q < 6; q++) {
        int j = q * 32 + lane;
        bool sel = (selmask >> q) & 1u;
        bool cen = (j == u) || (j == u + L_) || (j == u + 2 * L_);
        float h = (sel || cen) ? 1.f : 0.f;
        Hrow[j] = h;
        Htb[(long)j * M_ + i] = h;
        cnt += h;
    }
    #pragma unroll
    for (int off = 16; off > 0; off >>= 1) cnt += __shfl_xor_sync(0xffffffffu, cnt, off);
    if (lane == 0) g_dege[d * M_ + i] = cnt;
}

// deg_v[n] = sum_e H[e][n] = row sums of Ht (coalesced)
__global__ void degv_kernel() {
    int gw = (blockIdx.x * blockDim.x + threadIdx.x) >> 5;
    int lane = threadIdx.x & 31;
    if (gw >= D_ * M_) return;
    const float* r = g_Ht + (long)gw * M_;
    float s = 0.f;
    #pragma unroll
    for (int q = 0; q < 6; q++) s += r[q * 32 + lane];
    #pragma unroll
    for (int off = 16; off > 0; off >>= 1) s += __shfl_xor_sync(0xffffffffu, s, off);
    if (lane == 0) g_degv[gw] = s;
}

// ---------------- row normalization (fp32 + bf16 outputs) -------------------
__global__ void norm_kernel(const float* __restrict__ outc) {
    int gw = (blockIdx.x * blockDim.x + threadIdx.x) >> 5;
    int lane = threadIdx.x & 31;
    if (gw >= 3 * N_) return;
    int q = gw / N_, r = gw % N_;
    const float* src = outc + (long)r * (3 * G_) + q * G_;
    float vv[8]; float s = 0.f;
    #pragma unroll
    for (int c = 0; c < 8; c++) { vv[c] = src[lane + 32 * c]; s += vv[c] * vv[c]; }
    #pragma unroll
    for (int off = 16; off > 0; off >>= 1) s += __shfl_xor_sync(0xffffffffu, s, off);
    float inv = 1.f / (sqrtf(s) + 1e-8f);
    float* dst = g_xn + ((long)q * N_ + r) * G_;
    __nv_bfloat16* dsth = g_xnh + ((long)q * N_ + r) * G_;
    #pragma unroll
    for (int c = 0; c < 8; c++) {
        float x = vv[c] * inv;
        dst[lane + 32 * c] = x;
        dsth[lane + 32 * c] = __float2bfloat16(x);
    }
}

// ---------------- zero accumulators ----------------------------------------
__global__ void zero_kernel() {
    int tid = blockIdx.x * blockDim.x + threadIdx.x;
    if (tid < 3 * N_) { g_rowsum[tid] = 0.f; g_colsum[tid] = 0.f; }
    if (tid == 0) g_lossacc = 0.f;
}

// ---------------- tensor-core sim + fused exp row/col sums ------------------
__device__ __forceinline__ void mma16816(float* c, const unsigned* a,
                                         unsigned b0, unsigned b1) {
    asm volatile(
        "mma.sync.aligned.m16n8k16.row.col.f32.bf16.bf16.f32 "
        "{%0,%1,%2,%3},{%4,%5,%6,%7},{%8,%9},{%0,%1,%2,%3};"
        : "+f"(c[0]), "+f"(c[1]), "+f"(c[2]), "+f"(c[3])
        : "r"(a[0]), "r"(a[1]), "r"(a[2]), "r"(a[3]), "r"(b0), "r"(b1));
}

#define STR 40   // shared row stride in halves (32 data + 8 pad) -> conflict-free

__global__ __launch_bounds__(256)
void sim_mma_kernel() {
    const int pxA[3] = {0, 0, 1};
    const int pyA[3] = {1, 2, 2};
    const int pair = blockIdx.z;
    const __nv_bfloat16* Xm = g_xnh + (long)pxA[pair] * N_ * G_;
    const __nv_bfloat16* Ym = g_xnh + (long)pyA[pair] * N_ * G_;
    const int i0 = blockIdx.y * 128;
    const int j0 = blockIdx.x * 128;

    __shared__ __nv_bfloat16 As[128 * STR];
    __shared__ __nv_bfloat16 Bs[128 * STR];
    __shared__ float sRow[128];
    __shared__ float sCol[128];

    const int tid = threadIdx.x;
    const int lane = tid & 31;
    const int wid = tid >> 5;
    const int wm = wid >> 1;        // 0..3 -> 32-row strip
    const int wn = wid & 1;         // 0..1 -> 64-col strip
    const int g = lane >> 2;
    const int c2 = (lane & 3) << 1;

    if (tid < 128) { sRow[tid] = 0.f; sCol[tid] = 0.f; }

    float acc[2][8][4];
    #pragma unroll
    for (int mi = 0; mi < 2; mi++)
        #pragma unroll
        for (int ni = 0; ni < 8; ni++)
            #pragma unroll
            for (int r = 0; r < 4; r++) acc[mi][ni][r] = 0.f;

    for (int k0 = 0; k0 < G_; k0 += 32) {
        #pragma unroll
        for (int q = 0; q < 2; q++) {
            int qq = tid * 2 + q;           // 0..511
            int row = qq >> 2, kc = qq & 3; // 128 rows x 4 chunks of 8 halves
            *(uint4*)&As[row * STR + kc * 8] =
                *(const uint4*)(Xm + (long)(i0 + row) * G_ + k0 + kc * 8);
            *(uint4*)&Bs[row * STR + kc * 8] =
                *(const uint4*)(Ym + (long)(j0 + row) * G_ + k0 + kc * 8);
        }
        __syncthreads();
        #pragma unroll
        for (int kk = 0; kk < 32; kk += 16) {
            unsigned a[2][4];
            #pragma unroll
            for (int mi = 0; mi < 2; mi++) {
                int am = wm * 32 + mi * 16;
                a[mi][0] = *(const unsigned*)&As[(am + g)     * STR + kk + c2];
                a[mi][1] = *(const unsigned*)&As[(am + 8 + g) * STR + kk + c2];
                a[mi][2] = *(const unsigned*)&As[(am + g)     * STR + kk + 8 + c2];
                a[mi][3] = *(const unsigned*)&As[(am + 8 + g) * STR + kk + 8 + c2];
            }
            #pragma unroll
            for (int ni = 0; ni < 8; ni++) {
                int bn = wn * 64 + ni * 8;
                unsigned b0 = *(const unsigned*)&Bs[(bn + g) * STR + kk + c2];
                unsigned b1 = *(const unsigned*)&Bs[(bn + g) * STR + kk + 8 + c2];
                mma16816(acc[0][ni], a[0], b0, b1);
                mma16816(acc[1][ni], a[1], b0, b1);
            }
        }
        __syncthreads();
    }

    // exp(sim/tau)
    float e[2][8][4];
    #pragma unroll
    for (int mi = 0; mi < 2; mi++)
        #pragma unroll
        for (int ni = 0; ni < 8; ni++)
            #pragma unroll
            for (int r = 0; r < 4; r++)
                e[mi][ni][r] = __expf(acc[mi][ni][r] * INV_TAU);

    // row partial sums: C frag rows = {g, g+8}; reduce over lane&3 (cols)
    #pragma unroll
    for (int mi = 0; mi < 2; mi++)
        #pragma unroll
        for (int h = 0; h < 2; h++) {
            float s = 0.f;
            #pragma unroll
            for (int ni = 0; ni < 8; ni++)
                s += h ? (e[mi][ni][2] + e[mi][ni][3])
                       : (e[mi][ni][0] + e[mi][ni][1]);
            s += __shfl_xor_sync(0xffffffffu, s, 1);
            s += __shfl_xor_sync(0xffffffffu, s, 2);
            if ((lane & 3) == 0)
                atomicAdd(&sRow[wm * 32 + mi * 16 + h * 8 + g], s);
        }

    // col partial sums: C frag cols = 2*(lane&3)+p; reduce over lane>>2 (rows)
    #pragma unroll
    for (int ni = 0; ni < 8; ni++)
        #pragma unroll
        for (int p = 0; p < 2; p++) {
            float s = e[0][ni][p] + e[0][ni][p + 2] + e[1][ni][p] + e[1][ni][p + 2];
            s += __shfl_xor_sync(0xffffffffu, s, 4);
            s += __shfl_xor_sync(0xffffffffu, s, 8);
            s += __shfl_xor_sync(0xffffffffu, s, 16);
            if (lane < 4)
                atomicAdd(&sCol[wn * 64 + ni * 8 + lane * 2 + p], s);
        }

    __syncthreads();
    if (tid < 128) {
        atomicAdd(&g_rowsum[pair * N_ + i0 + tid], sRow[tid]);
        atomicAdd(&g_colsum[pair * N_ + j0 + tid], sCol[tid]);
    }
}

// ---------------- diagonal + loss accumulation -----------------------------
__global__ void loss_kernel() {
    int gw = (blockIdx.x * blockDim.x + threadIdx.x) >> 5;
    int lane = threadIdx.x & 31;
    if (gw >= 3 * N_) return;
    int p = gw / N_, i = gw % N_;
    const int pxA[3] = {0, 0, 1};
    const int pyA[3] = {1, 2, 2};
    const float* x = g_xn + ((long)pxA[p] * N_ + i) * G_;
    const float* y = g_xn + ((long)pyA[p] * N_ + i) * G_;
    float dot = 0.f;
    #pragma unroll
    for (int c = 0; c < 8; c++) dot += x[lane + 32 * c] * y[lane + 32 * c];
    #pragma unroll
    for (int off = 16; off > 0; off >>= 1) dot += __shfl_xor_sync(0xffffffffu, dot, off);
    if (lane == 0) {
        float ci = 2.f * dot * INV_TAU - logf(g_rowsum[p * N_ + i]) - logf(g_colsum[p * N_ + i]);
        atomicAdd(&g_lossacc, ci);
    }
}

__global__ void finish_kernel(float* out, int idx) {
    if (threadIdx.x == 0 && blockIdx.x == 0)
        out[idx] = -g_lossacc / (float)(2 * N_ * 3);
}

// ---------------- launch ----------------------------------------------------
extern "C" void kernel_launch(void* const* d_in, const int* in_sizes, int n_in,
                              void* d_out, int out_size) {
    const float* t   = (const float*)d_in[0];
    const float* a   = (const float*)d_in[1];
    const float* v   = (const float*)d_in[2];
    const float* Wfc = (const float*)d_in[3];
    const float* bfc = (const float*)d_in[4];
    const float* Wh  = (const float*)d_in[5];
    const float* bh  = (const float*)d_in[6];
    float* out = (float*)d_out;

    void *pf, *ph, *pht, *pde, *pdv, *px, *pe, *py;
    cudaGetSymbolAddress(&pf,  g_feat);
    cudaGetSymbolAddress(&ph,  g_H);
    cudaGetSymbolAddress(&pht, g_Ht);
    cudaGetSymbolAddress(&pde, g_dege);
    cudaGetSymbolAddress(&pdv, g_degv);
    cudaGetSymbolAddress(&px,  g_X);
    cudaGetSymbolAddress(&pe,  g_E);
    cudaGetSymbolAddress(&py,  g_Y);
    float* feat = (float*)pf;  float* H = (float*)ph;  float* Ht = (float*)pht;
    float* dege = (float*)pde; float* degv = (float*)pdv;
    float* X = (float*)px;     float* E = (float*)pe;  float* Y = (float*)py;

    pack_kernel<<<6144, 256>>>(t, a, v);
    zero_kernel<<<48, 256>>>();

    // gram[d] = feat_d @ feat_d^T, 3x-tf32 (fp32-equivalent for top-k)
    gram_tc<<<dim3(3, 3, D_), 128>>>();

    topk_kernel<<<1536, 256>>>();
    degv_kernel<<<1536, 256>>>();

    // X = feat @ W_fc + b_fc   (12288x256x512)
    gemm_tc<1><<<dim3(4, 192, 1), 128>>>(feat, Wfc, X,
        D_*M_, G_, DIM_, DIM_, G_, 0, 0, 0, bfc, nullptr, nullptr);

    // E = (H @ X) / deg_e   (batched 192x256x192)
    gemm_tc<2><<<dim3(4, 3, D_), 128>>>(H, X, E,
        M_, G_, M_, M_, G_,
        (long)M_*M_, (long)M_*G_, (long)M_*G_, nullptr, dege, nullptr);

    // Y = (Ht @ E) / deg_v
    gemm_tc<2><<<dim3(4, 3, D_), 128>>>(Ht, E, Y,
        M_, G_, M_, M_, G_,
        (long)M_*M_, (long)M_*G_, (long)M_*G_, nullptr, degv, nullptr);

    // out = relu(Y @ W_h + b_h), remapped into out_cat layout in d_out
    gemm_tc<3><<<dim3(4, 192, 1), 128>>>(Y, Wh, nullptr,
        D_*M_, G_, G_, G_, G_, 0, 0, 0, bh, nullptr, out);

    norm_kernel<<<1536, 256>>>(out);

    // all three contrastive sims on tensor cores, fused exp/row/col sums
    sim_mma_kernel<<<dim3(32, 32, 3), 256>>>();

    loss_kernel<<<1536, 256>>>();
    finish_kernel<<<1, 32>>>(out, out_size - 1);
}